// round 16
// baseline (speedup 1.0000x reference)
#include <cuda_runtime.h>
#include <cuda_fp16.h>
#include <cstdint>
#include <math.h>

// ---------------- problem dims ----------------
#define B_ROWS 16384
#define D_VIS  1024
#define D_H    256
#define E_NUM  4
#define G_NUM  5000
#define MAP_   128
#define SCVI_  30
#define N_GD2  (G_NUM*2)
#define NT_PAD 10112            // 79 tiles * 128

// ---------------- fp16 GEMM tile config ----------------
#define BM 128
#define BN 128
#define HBK 64                   // k-halfs per tile
#define STAGES 3
#define NTHREADS 256
#define H_AS 36                  // words per 64-half row (32 data + 4 pad)
#define H_HALF (128*H_AS)        // words per operand tile
#define H_STAGE (2*H_HALF)
#define H_SMEM (3*H_STAGE*4)     // 110592 B -> 2 CTA/SM
#define MAX_TILES 132
#define ES_STRIDE 132

// ---------------- scratch ----------------
__device__ __half g_four_h[(size_t)B_ROWS*2*MAP_];
__device__ __half g_vis_h [(size_t)B_ROWS*D_VIS];
__device__ float  g_z     [(size_t)B_ROWS*D_H];
__device__ __half g_z_h   [(size_t)B_ROWS*D_H];
__device__ __half g_zf_h  [(size_t)B_ROWS*D_H];
__device__ float  g_tpre  [(size_t)B_ROWS*D_H];
__device__ __half g_t_h   [(size_t)B_ROWS*D_H];
__device__ __half g_h     [(size_t)MAX_TILES*BM*1024];
__device__ int    g_eid [B_ROWS];
__device__ float  g_gate[B_ROWS];
__device__ int    g_perm[MAX_TILES*BM];
__device__ int    g_counts[E_NUM];
__device__ int    g_cursor[E_NUM];
__device__ int    g_padoff[E_NUM+1];
// transposed fp16 weights, [N][K] k-contiguous
__device__ __half w_pos_t [256*256];
__device__ __half w_img_t [256*1024];
__device__ __half w_e1_t  [E_NUM*1024*256];
__device__ __half w_e2_t  [E_NUM*256*1024];
__device__ __half w_gd1_t [256*256];
__device__ __half w_apfh_t[256*256];               // rows 0..127 ap1, 128..191 fh1, 192..255 zero
__device__ __half g_wt    [(size_t)NT_PAD*256];    // gd2

// ---------------- helpers ----------------
__device__ __forceinline__ float gelu_exact(float x) {
    return 0.5f * x * (1.0f + erff(x * 0.70710678118654752440f));
}
__device__ __forceinline__ void mma16h(float* c, const uint32_t* a, const uint32_t* b) {
    asm volatile("mma.sync.aligned.m16n8k16.row.col.f32.f16.f16.f32 "
        "{%0,%1,%2,%3}, {%4,%5,%6,%7}, {%8,%9}, {%0,%1,%2,%3};"
        : "+f"(c[0]), "+f"(c[1]), "+f"(c[2]), "+f"(c[3])
        : "r"(a[0]), "r"(a[1]), "r"(a[2]), "r"(a[3]), "r"(b[0]), "r"(b[1]));
}
__device__ __forceinline__ void ldsm4(uint32_t* r, uint32_t addr) {
    asm volatile("ldmatrix.sync.aligned.m8n8.x4.shared.b16 {%0,%1,%2,%3}, [%4];"
        : "=r"(r[0]), "=r"(r[1]), "=r"(r[2]), "=r"(r[3]) : "r"(addr));
}
__device__ __forceinline__ void cp_async16(float* dst_smem, const void* src, int src_bytes) {
    uint32_t d = (uint32_t)__cvta_generic_to_shared(dst_smem);
    asm volatile("cp.async.cg.shared.global [%0], [%1], 16, %2;\n"
                 :: "r"(d), "l"(src), "r"(src_bytes));
}
__device__ __forceinline__ void cp16f(float* dst_smem, const void* src) {
    uint32_t d = (uint32_t)__cvta_generic_to_shared(dst_smem);
    asm volatile("cp.async.cg.shared.global [%0], [%1], 16;\n" :: "r"(d), "l"(src));
}
__device__ __forceinline__ void cp_commit() { asm volatile("cp.async.commit_group;\n"); }
template<int N> __device__ __forceinline__ void cp_wait() {
    asm volatile("cp.async.wait_group %0;\n" :: "n"(N));
}

// ---------------- prep kernels ----------------
// tiled transpose fp32[K][N] -> fp16[NP][K]; rows N..NP zero-filled
__device__ __forceinline__ void trh_body(const float* __restrict__ src, __half* __restrict__ dst,
                                         int K, int N, int NP, int n0, int k0) {
    __shared__ float t[32][33];
    int tx = threadIdx.x & 31, ty = threadIdx.x >> 5;
    #pragma unroll
    for (int i = ty; i < 32; i += 8) {
        int n = n0 + tx;
        t[i][tx] = (n < N) ? src[(size_t)(k0 + i) * N + n] : 0.f;
    }
    __syncthreads();
    #pragma unroll
    for (int i = ty; i < 32; i += 8) {
        int n = n0 + i;
        if (n < NP) dst[(size_t)n * K + k0 + tx] = __float2half_rn(t[tx][i]);
    }
}

__global__ void k_trh(const float* __restrict__ src, __half* __restrict__ dst,
                      int K, int N, int NP, size_t sb, size_t db) {
    trh_body(src + blockIdx.z * sb, dst + blockIdx.z * db, K, N, NP,
             blockIdx.x * 32, blockIdx.y * 32);
}

// merged small transposes (all K=256): z=0 pos, z=1 gd1, z=2 ap1, z=3 fh1
__global__ void k_trh4(const float* __restrict__ pos_W, const float* __restrict__ gdW1,
                       const float* __restrict__ apW1,  const float* __restrict__ fhW1) {
    const float* src; __half* dst; int N, NP;
    switch (blockIdx.z) {
        case 0:  src = pos_W; dst = w_pos_t;  N = 256; NP = 256; break;
        case 1:  src = gdW1;  dst = w_gd1_t;  N = 256; NP = 256; break;
        case 2:  src = apW1;  dst = w_apfh_t; N = 128; NP = 128; break;
        default: src = fhW1;  dst = w_apfh_t + (size_t)128*256; N = 64; NP = 128; break;
    }
    trh_body(src, dst, 256, N, NP, blockIdx.x * 32, blockIdx.y * 32);
}

__global__ void k_vish(const float* __restrict__ src, int n4) {
    int i = blockIdx.x * blockDim.x + threadIdx.x;
    if (i >= n4) return;
    float4 v = ((const float4*)src)[i];
    __half2 a = __floats2half2_rn(v.x, v.y);
    __half2 b = __floats2half2_rn(v.z, v.w);
    uint2 o = make_uint2(*(uint32_t*)&a, *(uint32_t*)&b);
    ((uint2*)g_vis_h)[i] = o;
}

// ---------------- generic fp16 GEMM (ldmatrix fragments) ----------------
template<bool PERM>
__device__ __forceinline__ void issue_h(
    float* stage, const __half* __restrict__ A, int K,
    const __half* __restrict__ Wt,
    int m0, int n0, int k0, const int* __restrict__ perm)
{
    float* As = stage;
    float* Bs = stage + H_HALF;
    const int tid = threadIdx.x;
    int r = tid >> 1;
    int jb = (tid & 1) * 4;
    if (PERM) {
        int rowg = perm[m0 + r];
        const __half* sA = A + (size_t)(rowg < 0 ? 0 : rowg) * K + k0;
        int sz = (rowg >= 0) ? 16 : 0;
        #pragma unroll
        for (int i = 0; i < 4; i++)
            cp_async16(As + r*H_AS + (jb+i)*4, sA + (jb+i)*8, sz);
    } else {
        const __half* sA = A + (size_t)(m0 + r) * K + k0;
        #pragma unroll
        for (int i = 0; i < 4; i++)
            cp16f(As + r*H_AS + (jb+i)*4, sA + (jb+i)*8);
    }
    const __half* sB = Wt + (size_t)(n0 + r) * K + k0;
    #pragma unroll
    for (int i = 0; i < 4; i++)
        cp16f(Bs + r*H_AS + (jb+i)*4, sB + (jb+i)*8);
}

template<bool PERM>
__device__ __forceinline__ void gemm_f16(
    float acc[4][4][4],
    const __half* __restrict__ A, int K,
    const __half* __restrict__ Wt,
    int m0, int n0, const int* __restrict__ perm, float* sm)
{
    const int KT = K / HBK;
    #pragma unroll
    for (int s = 0; s < STAGES-1; s++) {
        if (s < KT) issue_h<PERM>(sm + s*H_STAGE, A, K, Wt, m0, n0, s*HBK, perm);
        cp_commit();
    }
    cp_wait<STAGES-2>();
    __syncthreads();

    const int warp = threadIdx.x >> 5, lane = threadIdx.x & 31;
    const int mw = (warp >> 2) * 64, nw = (warp & 3) * 32;

    // ldmatrix per-lane base addresses (bytes, shared space)
    const uint32_t smem_u32 = (uint32_t)__cvta_generic_to_shared(sm);
    const int lr = lane & 7, sub01 = (lane >> 3) & 1, sub2 = lane >> 4;
    const uint32_t a_base = smem_u32 + (uint32_t)(((mw + sub01*8 + lr) * H_AS + sub2*4) * 4);
    const uint32_t b_base = smem_u32 + (uint32_t)(((nw + sub01*8 + lr) * H_AS + sub2*4) * 4)
                          + (uint32_t)(H_HALF * 4);

    for (int kt = 0; kt < KT; kt++) {
        const uint32_t stg = (uint32_t)((kt%STAGES) * H_STAGE * 4);
        #pragma unroll
        for (int s = 0; s < HBK/16; s++) {
            const uint32_t koff = stg + (uint32_t)(s * 32);   // s*8 words * 4B
            uint32_t af[4][4], bq[2][4];
            #pragma unroll
            for (int mi = 0; mi < 4; mi++)
                ldsm4(af[mi], a_base + koff + (uint32_t)(mi * 16 * H_AS * 4));
            ldsm4(bq[0], b_base + koff);
            ldsm4(bq[1], b_base + koff + (uint32_t)(16 * H_AS * 4));
            // bq[p] = { b0(ni=2p), b0(2p+1), b1(2p), b1(2p+1) }
            uint32_t b0[2] = { bq[0][0], bq[0][2] };
            uint32_t b1[2] = { bq[0][1], bq[0][3] };
            uint32_t b2[2] = { bq[1][0], bq[1][2] };
            uint32_t b3[2] = { bq[1][1], bq[1][3] };
            #pragma unroll
            for (int mi = 0; mi < 4; mi++) {
                mma16h(acc[mi][0], af[mi], b0);
                mma16h(acc[mi][1], af[mi], b1);
                mma16h(acc[mi][2], af[mi], b2);
                mma16h(acc[mi][3], af[mi], b3);
            }
        }
        int pre = kt + STAGES - 1;
        if (pre < KT) issue_h<PERM>(sm + (pre%STAGES)*H_STAGE, A, K, Wt, m0, n0, pre*HBK, perm);
        cp_commit();
        cp_wait<STAGES-2>();
        __syncthreads();
    }
}

#define FRAG_IDX \
    const int warp = threadIdx.x >> 5, lane = threadIdx.x & 31; \
    const int mw = (warp >> 2) * 64, nw = (warp & 3) * 32; \
    const int g = lane >> 2, t4 = lane & 3;

// ---------------- stage kernels ----------------
__global__ void k_four(const float* __restrict__ pos, const float* __restrict__ fB) {
    int gtid = blockIdx.x * 256 + threadIdx.x;
    if (gtid < MAX_TILES*BM) g_perm[gtid] = -1;
    if (gtid < E_NUM) { g_counts[gtid] = 0; g_cursor[gtid] = 0; }

    int w = threadIdx.x >> 5, lane = threadIdx.x & 31;
    int row = blockIdx.x * 8 + w;
    float p0 = pos[row*3+0], p1 = pos[row*3+1], p2 = pos[row*3+2];
    #pragma unroll
    for (int i = 0; i < 4; i++) {
        int c = lane + 32*i;
        float xp = 6.283185307179586477f * (p0*fB[c] + p1*fB[MAP_+c] + p2*fB[2*MAP_+c]);
        float s, co;
        sincosf(xp, &s, &co);
        g_four_h[(size_t)row*256 + c]       = __float2half_rn(s);
        g_four_h[(size_t)row*256 + 128 + c] = __float2half_rn(co);
    }
}

__global__ void __launch_bounds__(NTHREADS, 2)
k_gemm_z(const float* __restrict__ img_b, const float* __restrict__ pos_b) {
    extern __shared__ float sm[];
    float acc[4][4][4] = {};
    int m0 = blockIdx.y * BM, n0 = blockIdx.x * BN;
    FRAG_IDX
    gemm_f16<false>(acc, g_four_h, 256, w_pos_t, m0, n0, nullptr, sm);
    #pragma unroll
    for (int mi = 0; mi < 4; mi++)
        #pragma unroll
        for (int ni = 0; ni < 4; ni++) {
            int c0 = n0 + nw + ni*8 + t4*2;
            acc[mi][ni][0] = gelu_exact(acc[mi][ni][0] + pos_b[c0]);
            acc[mi][ni][1] = gelu_exact(acc[mi][ni][1] + pos_b[c0+1]);
            acc[mi][ni][2] = gelu_exact(acc[mi][ni][2] + pos_b[c0]);
            acc[mi][ni][3] = gelu_exact(acc[mi][ni][3] + pos_b[c0+1]);
        }
    gemm_f16<false>(acc, g_vis_h, 1024, w_img_t, m0, n0, nullptr, sm);
    #pragma unroll
    for (int mi = 0; mi < 4; mi++)
        #pragma unroll
        for (int ni = 0; ni < 4; ni++) {
            int r0 = m0 + mw + mi*16 + g, r1 = r0 + 8;
            int c0 = n0 + nw + ni*8 + t4*2, c1 = c0 + 1;
            float v00 = acc[mi][ni][0] + img_b[c0];
            float v01 = acc[mi][ni][1] + img_b[c1];
            float v10 = acc[mi][ni][2] + img_b[c0];
            float v11 = acc[mi][ni][3] + img_b[c1];
            g_z[(size_t)r0*256 + c0] = v00;  g_z_h[(size_t)r0*256 + c0] = __float2half_rn(v00);
            g_z[(size_t)r0*256 + c1] = v01;  g_z_h[(size_t)r0*256 + c1] = __float2half_rn(v01);
            g_z[(size_t)r1*256 + c0] = v10;  g_z_h[(size_t)r1*256 + c0] = __float2half_rn(v10);
            g_z[(size_t)r1*256 + c1] = v11;  g_z_h[(size_t)r1*256 + c1] = __float2half_rn(v11);
        }
}

__global__ void k_router(const float* __restrict__ grad,
                         const float* __restrict__ rW, const float* __restrict__ rb) {
    int w = threadIdx.x >> 5, lane = threadIdx.x & 31;
    int row = blockIdx.x * 8 + w;
    float4 s = make_float4(0.f,0.f,0.f,0.f);
    #pragma unroll
    for (int i = 0; i < 8; i++) {
        int k = lane + 32*i;
        float zv = g_z[(size_t)row*256 + k];
        float4 wv = *(const float4*)(rW + k*4);
        s.x = fmaf(zv, wv.x, s.x); s.y = fmaf(zv, wv.y, s.y);
        s.z = fmaf(zv, wv.z, s.z); s.w = fmaf(zv, wv.w, s.w);
    }
    #pragma unroll
    for (int off = 16; off; off >>= 1) {
        s.x += __shfl_down_sync(0xffffffffu, s.x, off);
        s.y += __shfl_down_sync(0xffffffffu, s.y, off);
        s.z += __shfl_down_sync(0xffffffffu, s.z, off);
        s.w += __shfl_down_sync(0xffffffffu, s.w, off);
    }
    if (lane == 0) {
        float gv = grad[row];
        float4 wg = *(const float4*)(rW + 256*4);
        float l0 = s.x + gv*wg.x + rb[0];
        float l1 = s.y + gv*wg.y + rb[1];
        float l2 = s.z + gv*wg.z + rb[2];
        float l3 = s.w + gv*wg.w + rb[3];
        float m = l0; int am = 0;
        if (l1 > m) { m = l1; am = 1; }
        if (l2 > m) { m = l2; am = 2; }
        if (l3 > m) { m = l3; am = 3; }
        float sum = expf(l0-m) + expf(l1-m) + expf(l2-m) + expf(l3-m);
        g_eid[row]  = am;
        g_gate[row] = 1.0f / sum;
        atomicAdd(&g_counts[am], 1);
    }
}

__global__ void k_offsets() {
    int off = 0;
    for (int e = 0; e < E_NUM; e++) {
        g_padoff[e] = off;
        off += ((g_counts[e] + BM - 1) / BM) * BM;
    }
    g_padoff[E_NUM] = off;
}

__global__ void k_scatter() {
    int row = blockIdx.x * 256 + threadIdx.x;
    int e = g_eid[row];
    int slot = g_padoff[e] + atomicAdd(&g_cursor[e], 1);
    g_perm[slot] = row;
}

__device__ __forceinline__ int tile_expert(int m0) {
    int e = 0;
    while (e < E_NUM-1 && m0 >= g_padoff[e+1]) e++;
    return e;
}

__global__ void __launch_bounds__(NTHREADS, 2)
k_moe1(const float* __restrict__ eb1) {
    int m0 = blockIdx.y * BM;
    if (m0 >= g_padoff[E_NUM]) return;
    extern __shared__ float sm[];
    int e = tile_expert(m0);
    const __half* W1 = w_e1_t + (size_t)e * 1024 * 256;
    float acc[4][4][4] = {};
    int n0 = blockIdx.x * BN;
    gemm_f16<true>(acc, g_z_h, 256, W1, m0, n0, g_perm, sm);
    FRAG_IDX
    #pragma unroll
    for (int mi = 0; mi < 4; mi++)
        #pragma unroll
        for (int ni = 0; ni < 4; ni++) {
            int r0 = m0 + mw + mi*16 + g, r1 = r0 + 8;
            int c0 = n0 + nw + ni*8 + t4*2, c1 = c0 + 1;
            g_h[(size_t)r0*1024 + c0] = __float2half_rn(gelu_exact(acc[mi][ni][0] + eb1[e*1024 + c0]));
            g_h[(size_t)r0*1024 + c1] = __float2half_rn(gelu_exact(acc[mi][ni][1] + eb1[e*1024 + c1]));
            g_h[(size_t)r1*1024 + c0] = __float2half_rn(gelu_exact(acc[mi][ni][2] + eb1[e*1024 + c0]));
            g_h[(size_t)r1*1024 + c1] = __float2half_rn(gelu_exact(acc[mi][ni][3] + eb1[e*1024 + c1]));
        }
}

__global__ void __launch_bounds__(NTHREADS, 2)
k_moe2(const float* __restrict__ eb2) {
    int m0 = blockIdx.y * BM;
    if (m0 >= g_padoff[E_NUM]) return;
    extern __shared__ float sm[];
    int e = tile_expert(m0);
    const __half* W2 = w_e2_t + (size_t)e * 256 * 1024;
    float acc[4][4][4] = {};
    int n0 = blockIdx.x * BN;
    gemm_f16<false>(acc, g_h, 1024, W2, m0, n0, nullptr, sm);
    FRAG_IDX
    #pragma unroll
    for (int mi = 0; mi < 4; mi++)
        #pragma unroll
        for (int ni = 0; ni < 4; ni++) {
            int s0 = m0 + mw + mi*16 + g, s1 = s0 + 8;
            int c0 = n0 + nw + ni*8 + t4*2, c1 = c0 + 1;
            int r0 = g_perm[s0], r1 = g_perm[s1];
            if (r0 >= 0) {
                float gate = g_gate[r0];
                g_zf_h[(size_t)r0*256 + c0] = __float2half_rn(g_z[(size_t)r0*256 + c0] + gate*(acc[mi][ni][0] + eb2[e*256 + c0]));
                g_zf_h[(size_t)r0*256 + c1] = __float2half_rn(g_z[(size_t)r0*256 + c1] + gate*(acc[mi][ni][1] + eb2[e*256 + c1]));
            }
            if (r1 >= 0) {
                float gate = g_gate[r1];
                g_zf_h[(size_t)r1*256 + c0] = __float2half_rn(g_z[(size_t)r1*256 + c0] + gate*(acc[mi][ni][2] + eb2[e*256 + c0]));
                g_zf_h[(size_t)r1*256 + c1] = __float2half_rn(g_z[(size_t)r1*256 + c1] + gate*(acc[mi][ni][3] + eb2[e*256 + c1]));
            }
        }
}

__global__ void __launch_bounds__(NTHREADS, 2)
k_tpre(const float* __restrict__ b) {
    extern __shared__ float sm[];
    float acc[4][4][4] = {};
    int m0 = blockIdx.y * BM, n0 = blockIdx.x * BN;
    gemm_f16<false>(acc, g_zf_h, 256, w_gd1_t, m0, n0, nullptr, sm);
    FRAG_IDX
    #pragma unroll
    for (int mi = 0; mi < 4; mi++)
        #pragma unroll
        for (int ni = 0; ni < 4; ni++) {
            int r0 = m0 + mw + mi*16 + g, r1 = r0 + 8;
            int c0 = n0 + nw + ni*8 + t4*2, c1 = c0 + 1;
            g_tpre[(size_t)r0*256 + c0] = acc[mi][ni][0] + b[c0];
            g_tpre[(size_t)r0*256 + c1] = acc[mi][ni][1] + b[c1];
            g_tpre[(size_t)r1*256 + c0] = acc[mi][ni][2] + b[c0];
            g_tpre[(size_t)r1*256 + c1] = acc[mi][ni][3] + b[c1];
        }
}

__global__ void k_ln(const float* __restrict__ gam, const float* __restrict__ beta) {
    int w = threadIdx.x >> 5, lane = threadIdx.x & 31;
    int row = blockIdx.x * 8 + w;
    float v[8]; float s = 0.f;
    #pragma unroll
    for (int i = 0; i < 8; i++) {
        v[i] = g_tpre[(size_t)row*256 + lane + 32*i];
        s += v[i];
    }
    #pragma unroll
    for (int off = 16; off; off >>= 1) s += __shfl_xor_sync(0xffffffffu, s, off);
    float mean = s * (1.f/256.f);
    float s2 = 0.f;
    #pragma unroll
    for (int i = 0; i < 8; i++) { float d = v[i] - mean; s2 = fmaf(d, d, s2); }
    #pragma unroll
    for (int off = 16; off; off >>= 1) s2 += __shfl_xor_sync(0xffffffffu, s2, off);
    float rs = rsqrtf(s2 * (1.f/256.f) + 1e-5f);
    #pragma unroll
    for (int i = 0; i < 8; i++) {
        int k = lane + 32*i;
        g_t_h[(size_t)row*256 + k] = __float2half_rn(gelu_exact(gam[k] * (v[i] - mean) * rs + beta[k]));
    }
}

// gd2 with coalesced smem-staged epilogue
__global__ void __launch_bounds__(NTHREADS, 2)
k_gd2(const float* __restrict__ b2,
      const float* __restrict__ lib, float* __restrict__ out) {
    extern __shared__ float sm[];
    float acc[4][4][4] = {};
    int m0 = blockIdx.y * BM, n0 = blockIdx.x * BN;
    gemm_f16<false>(acc, g_t_h, 256, g_wt, m0, n0, nullptr, sm);
    FRAG_IDX
    float* es = sm;
    #pragma unroll
    for (int mi = 0; mi < 4; mi++)
        #pragma unroll
        for (int ni = 0; ni < 4; ni++) {
            int r0 = mw + mi*16 + g, r1 = r0 + 8;
            int c0 = nw + ni*8 + t4*2, c1 = c0 + 1;
            es[r0*ES_STRIDE + c0] = acc[mi][ni][0];
            es[r0*ES_STRIDE + c1] = acc[mi][ni][1];
            es[r1*ES_STRIDE + c0] = acc[mi][ni][2];
            es[r1*ES_STRIDE + c1] = acc[mi][ni][3];
        }
    __syncthreads();
    const size_t THETA_OFF = (size_t)B_ROWS * G_NUM;
    int gbase = n0 >> 1;
    for (int r = warp; r < BM; r += 8) {
        int row = m0 + r;
        float lb = lib[row];
        #pragma unroll
        for (int j = 0; j < 2; j++) {
            int gcol = j*32 + lane;
            int col0 = 2*gcol, col1 = col0 + 1;
            if (n0 + col0 < N_GD2) {
                float v = es[r*ES_STRIDE + col0] + b2[n0 + col0];
                float sp = (v > 20.f) ? v : log1pf(expf(v));
                out[(size_t)row*G_NUM + gbase + gcol] = sp * lb + 1e-6f;
            }
            if (n0 + col1 < N_GD2) {
                float v = es[r*ES_STRIDE + col1] + b2[n0 + col1];
                float sp = (v > 20.f) ? v : log1pf(expf(v));
                out[THETA_OFF + (size_t)row*G_NUM + gbase + gcol] = sp + 1e-6f;
            }
        }
    }
}

// merged align + func hidden, WITH fused second-stage heads.
// block n0=0: full a1 (128 cols) -> align output. block n0=128: f1 (64 cols) -> func output.
__global__ void __launch_bounds__(NTHREADS, 2)
k_apfh(const float* __restrict__ apb, const float* __restrict__ fhb,
       const float* __restrict__ apW2, const float* __restrict__ apb2,
       const float* __restrict__ fhW2, const float* __restrict__ fhb2,
       float* __restrict__ out) {
    extern __shared__ float sm[];
    float acc[4][4][4] = {};
    int m0 = blockIdx.y * BM, n0 = blockIdx.x * BN;
    gemm_f16<false>(acc, g_zf_h, 256, w_apfh_t, m0, n0, nullptr, sm);
    FRAG_IDX
    float* es = sm;                       // 128 x ES_STRIDE activation tile
    float* W2s = sm + BM*ES_STRIDE;       // align W2 [128][30]
    float* bs  = W2s + 128*SCVI_;
    const bool is_ap = (n0 == 0);
    #pragma unroll
    for (int mi = 0; mi < 4; mi++)
        #pragma unroll
        for (int ni = 0; ni < 4; ni++) {
            int r0 = mw + mi*16 + g, r1 = r0 + 8;
            int c0 = nw + ni*8 + t4*2, c1 = c0 + 1;   // local col
            #pragma unroll
            for (int q = 0; q < 4; q++) {
                int r = (q & 2) ? r1 : r0;
                int c = (q & 1) ? c1 : c0;
                float v = acc[mi][ni][q];
                if (is_ap)
                    es[r*ES_STRIDE + c] = gelu_exact(v + apb[c]);
                else if (c < 64)
                    es[r*ES_STRIDE + c] = gelu_exact(v + fhb[c]);
            }
        }
    if (is_ap) {
        for (int i = threadIdx.x; i < 128*SCVI_; i += NTHREADS) W2s[i] = apW2[i];
        if (threadIdx.x < SCVI_) bs[threadIdx.x] = apb2[threadIdx.x];
    }
    __syncthreads();

    if (is_ap) {
        const size_t ALIGN_OFF = 2ull * B_ROWS * G_NUM + B_ROWS;
        int c = lane;
        for (int r = warp; r < BM; r += 8) {
            if (c < SCVI_) {
                float s = bs[c];
                #pragma unroll 4
                for (int k = 0; k < 128; k++)
                    s = fmaf(es[r*ES_STRIDE + k], W2s[k*SCVI_ + c], s);
                out[ALIGN_OFF + (size_t)(m0 + r)*SCVI_ + c] = s;
            }
        }
    } else {
        const size_t FUNC_OFF = 2ull * B_ROWS * G_NUM;
        float w0 = fhW2[lane], w1 = fhW2[lane + 32];
        float bb = fhb2[0];
        for (int r = warp; r < BM; r += 8) {
            float v = es[r*ES_STRIDE + lane] * w0 + es[r*ES_STRIDE + lane + 32] * w1;
            #pragma unroll
            for (int off = 16; off; off >>= 1) v += __shfl_down_sync(0xffffffffu, v, off);
            if (lane == 0)
                out[FUNC_OFF + (m0 + r)] = 1.f / (1.f + expf(-(v + bb)));
        }
    }
}

// ---------------- launch ----------------
extern "C" void kernel_launch(void* const* d_in, const int* in_sizes, int n_in,
                              void* d_out, int out_size) {
    const float* vis   = (const float*)d_in[0];
    const float* pos   = (const float*)d_in[1];
    const float* grad  = (const float*)d_in[2];
    const float* lib   = (const float*)d_in[3];
    const float* fB    = (const float*)d_in[4];
    const float* img_W = (const float*)d_in[5];
    const float* img_b = (const float*)d_in[6];
    const float* pos_W = (const float*)d_in[7];
    const float* pos_b = (const float*)d_in[8];
    const float* rW    = (const float*)d_in[9];
    const float* rb    = (const float*)d_in[10];
    const float* eW1   = (const float*)d_in[11];
    const float* eb1   = (const float*)d_in[12];
    const float* eW2   = (const float*)d_in[13];
    const float* eb2   = (const float*)d_in[14];
    const float* gdW1  = (const float*)d_in[15];
    const float* gdb1  = (const float*)d_in[16];
    const float* gdg   = (const float*)d_in[17];
    const float* gdbe  = (const float*)d_in[18];
    const float* gdW2  = (const float*)d_in[19];
    const float* gdb2  = (const float*)d_in[20];
    const float* apW1  = (const float*)d_in[21];
    const float* apb1  = (const float*)d_in[22];
    const float* apW2  = (const float*)d_in[23];
    const float* apb2  = (const float*)d_in[24];
    const float* fhW1  = (const float*)d_in[25];
    const float* fhb1  = (const float*)d_in[26];
    const float* fhW2  = (const float*)d_in[27];
    const float* fhb2  = (const float*)d_in[28];
    float* out = (float*)d_out;

    cudaFuncSetAttribute(k_gemm_z, cudaFuncAttributeMaxDynamicSharedMemorySize, H_SMEM);
    cudaFuncSetAttribute(k_moe1,   cudaFuncAttributeMaxDynamicSharedMemorySize, H_SMEM);
    cudaFuncSetAttribute(k_moe2,   cudaFuncAttributeMaxDynamicSharedMemorySize, H_SMEM);
    cudaFuncSetAttribute(k_tpre,   cudaFuncAttributeMaxDynamicSharedMemorySize, H_SMEM);
    cudaFuncSetAttribute(k_gd2,    cudaFuncAttributeMaxDynamicSharedMemorySize, H_SMEM);
    cudaFuncSetAttribute(k_apfh,   cudaFuncAttributeMaxDynamicSharedMemorySize, H_SMEM);

    __half *iw, *e1w, *e2w, *g2w;
    cudaGetSymbolAddress((void**)&iw,  w_img_t);
    cudaGetSymbolAddress((void**)&e1w, w_e1_t);
    cudaGetSymbolAddress((void**)&e2w, w_e2_t);
    cudaGetSymbolAddress((void**)&g2w, g_wt);

    // weight prep
    k_trh4<<<dim3(8, 8, 4), 256>>>(pos_W, gdW1, apW1, fhW1);
    k_trh<<<dim3(8, 32, 1), 256>>>(img_W, iw, 1024, 256, 256, 0, 0);
    k_trh<<<dim3(32, 8, E_NUM), 256>>>(eW1, e1w, 256, 1024, 1024, (size_t)256*1024, (size_t)1024*256);
    k_trh<<<dim3(8, 32, E_NUM), 256>>>(eW2, e2w, 1024, 256, 256, (size_t)1024*256, (size_t)256*1024);
    k_trh<<<dim3(316, 8, 1), 256>>>(gdW2, g2w, 256, N_GD2, NT_PAD, 0, 0);
    k_vish<<<(B_ROWS*D_VIS/4 + 255)/256, 256>>>(vis, B_ROWS*D_VIS/4);

    k_four   <<<B_ROWS/8, 256>>>(pos, fB);
    k_gemm_z <<<dim3(2, B_ROWS/BM), NTHREADS, H_SMEM>>>(img_b, pos_b);
    k_router <<<B_ROWS/8, 256>>>(grad, rW, rb);
    k_offsets<<<1,1>>>();
    k_scatter<<<B_ROWS/256, 256>>>();
    k_moe1   <<<dim3(8, MAX_TILES), NTHREADS, H_SMEM>>>(eb1);
    k_moe2   <<<dim3(2, MAX_TILES), NTHREADS, H_SMEM>>>(eb2);
    k_tpre   <<<dim3(2, B_ROWS/BM), NTHREADS, H_SMEM>>>(gdb1);
    k_ln     <<<B_ROWS/8, 256>>>(gdg, gdbe);
    k_gd2    <<<dim3(NT_PAD/BN, B_ROWS/BM), NTHREADS, H_SMEM>>>(gdb2, lib, out);
    k_apfh   <<<dim3(2, B_ROWS/BM), NTHREADS, H_SMEM>>>(apb1, fhb1, apW2, apb2, fhW2, fhb2, out);
}

// round 17
// speedup vs baseline: 1.0382x; 1.0382x over previous
#include <cuda_runtime.h>
#include <cuda_fp16.h>
#include <cstdint>
#include <math.h>

// ---------------- problem dims ----------------
#define B_ROWS 16384
#define D_VIS  1024
#define D_H    256
#define E_NUM  4
#define G_NUM  5000
#define MAP_   128
#define SCVI_  30
#define N_GD2  (G_NUM*2)
#define NT_PAD 10112            // 79 tiles * 128

// ---------------- fp16 GEMM tile config (R15) ----------------
#define BM 128
#define BN 128
#define HBK 64                   // k-halfs per tile
#define STAGES 3
#define NTHREADS 256
#define H_AS 36                  // words per 64-half row (32 data + 4 pad)
#define H_HALF (128*H_AS)        // words per operand tile
#define H_STAGE (2*H_HALF)
#define H_SMEM (3*H_STAGE*4)     // 110592 B -> 2 CTA/SM
#define MAX_TILES 132
#define ES_STRIDE 132

// ---------------- scratch ----------------
__device__ __half g_four_h[(size_t)B_ROWS*2*MAP_];
__device__ __half g_vis_h [(size_t)B_ROWS*D_VIS];
__device__ float  g_z     [(size_t)B_ROWS*D_H];
__device__ __half g_z_h   [(size_t)B_ROWS*D_H];
__device__ __half g_zf_h  [(size_t)B_ROWS*D_H];
__device__ float  g_tpre  [(size_t)B_ROWS*D_H];
__device__ __half g_t_h   [(size_t)B_ROWS*D_H];
__device__ __half g_h     [(size_t)MAX_TILES*BM*1024];
__device__ int    g_eid [B_ROWS];
__device__ float  g_gate[B_ROWS];
__device__ int    g_perm[MAX_TILES*BM];
__device__ int    g_counts[E_NUM];
__device__ int    g_cursor[E_NUM];
__device__ int    g_padoff[E_NUM+1];
// transposed fp16 weights, [N][K] k-contiguous
__device__ __half w_pos_t [256*256];
__device__ __half w_img_t [256*1024];
__device__ __half w_e1_t  [E_NUM*1024*256];
__device__ __half w_e2_t  [E_NUM*256*1024];
__device__ __half w_gd1_t [256*256];
__device__ __half w_apfh_t[256*256];               // rows 0..127 ap1, 128..191 fh1, 192..255 zero
__device__ __half g_wt    [(size_t)NT_PAD*256];    // gd2

// ---------------- helpers ----------------
__device__ __forceinline__ float gelu_exact(float x) {
    return 0.5f * x * (1.0f + erff(x * 0.70710678118654752440f));
}
__device__ __forceinline__ void mma16h(float* c, const uint32_t* a, const uint32_t* b) {
    asm volatile("mma.sync.aligned.m16n8k16.row.col.f32.f16.f16.f32 "
        "{%0,%1,%2,%3}, {%4,%5,%6,%7}, {%8,%9}, {%0,%1,%2,%3};"
        : "+f"(c[0]), "+f"(c[1]), "+f"(c[2]), "+f"(c[3])
        : "r"(a[0]), "r"(a[1]), "r"(a[2]), "r"(a[3]), "r"(b[0]), "r"(b[1]));
}
__device__ __forceinline__ void cp_async16(float* dst_smem, const void* src, int src_bytes) {
    uint32_t d = (uint32_t)__cvta_generic_to_shared(dst_smem);
    asm volatile("cp.async.cg.shared.global [%0], [%1], 16, %2;\n"
                 :: "r"(d), "l"(src), "r"(src_bytes));
}
__device__ __forceinline__ void cp16f(float* dst_smem, const void* src) {
    uint32_t d = (uint32_t)__cvta_generic_to_shared(dst_smem);
    asm volatile("cp.async.cg.shared.global [%0], [%1], 16;\n" :: "r"(d), "l"(src));
}
__device__ __forceinline__ void cp_commit() { asm volatile("cp.async.commit_group;\n"); }
template<int N> __device__ __forceinline__ void cp_wait() {
    asm volatile("cp.async.wait_group %0;\n" :: "n"(N));
}

// ---------------- prep kernels ----------------
__device__ __forceinline__ void trh_body(const float* __restrict__ src, __half* __restrict__ dst,
                                         int K, int N, int NP, int n0, int k0) {
    __shared__ float t[32][33];
    int tx = threadIdx.x & 31, ty = threadIdx.x >> 5;
    #pragma unroll
    for (int i = ty; i < 32; i += 8) {
        int n = n0 + tx;
        t[i][tx] = (n < N) ? src[(size_t)(k0 + i) * N + n] : 0.f;
    }
    __syncthreads();
    #pragma unroll
    for (int i = ty; i < 32; i += 8) {
        int n = n0 + i;
        if (n < NP) dst[(size_t)n * K + k0 + tx] = __float2half_rn(t[tx][i]);
    }
}

__global__ void k_trh(const float* __restrict__ src, __half* __restrict__ dst,
                      int K, int N, int NP, size_t sb, size_t db) {
    trh_body(src + blockIdx.z * sb, dst + blockIdx.z * db, K, N, NP,
             blockIdx.x * 32, blockIdx.y * 32);
}

// merged small transposes (all K=256): z=0 pos, z=1 gd1, z=2 ap1, z=3 fh1
__global__ void k_trh4(const float* __restrict__ pos_W, const float* __restrict__ gdW1,
                       const float* __restrict__ apW1,  const float* __restrict__ fhW1) {
    const float* src; __half* dst; int N, NP;
    switch (blockIdx.z) {
        case 0:  src = pos_W; dst = w_pos_t;  N = 256; NP = 256; break;
        case 1:  src = gdW1;  dst = w_gd1_t;  N = 256; NP = 256; break;
        case 2:  src = apW1;  dst = w_apfh_t; N = 128; NP = 128; break;
        default: src = fhW1;  dst = w_apfh_t + (size_t)128*256; N = 64; NP = 128; break;
    }
    trh_body(src, dst, 256, N, NP, blockIdx.x * 32, blockIdx.y * 32);
}

__global__ void k_vish(const float* __restrict__ src, int n4) {
    int i = blockIdx.x * blockDim.x + threadIdx.x;
    if (i >= n4) return;
    float4 v = ((const float4*)src)[i];
    __half2 a = __floats2half2_rn(v.x, v.y);
    __half2 b = __floats2half2_rn(v.z, v.w);
    uint2 o = make_uint2(*(uint32_t*)&a, *(uint32_t*)&b);
    ((uint2*)g_vis_h)[i] = o;
}

// ---------------- generic fp16 GEMM (R15 scalar-LDS fragments) ----------------
template<bool PERM>
__device__ __forceinline__ void issue_h(
    float* stage, const __half* __restrict__ A, int K,
    const __half* __restrict__ Wt,
    int m0, int n0, int k0, const int* __restrict__ perm)
{
    float* As = stage;
    float* Bs = stage + H_HALF;
    const int tid = threadIdx.x;
    int r = tid >> 1;
    int jb = (tid & 1) * 4;
    if (PERM) {
        int rowg = perm[m0 + r];
        const __half* sA = A + (size_t)(rowg < 0 ? 0 : rowg) * K + k0;
        int sz = (rowg >= 0) ? 16 : 0;
        #pragma unroll
        for (int i = 0; i < 4; i++)
            cp_async16(As + r*H_AS + (jb+i)*4, sA + (jb+i)*8, sz);
    } else {
        const __half* sA = A + (size_t)(m0 + r) * K + k0;
        #pragma unroll
        for (int i = 0; i < 4; i++)
            cp16f(As + r*H_AS + (jb+i)*4, sA + (jb+i)*8);
    }
    const __half* sB = Wt + (size_t)(n0 + r) * K + k0;
    #pragma unroll
    for (int i = 0; i < 4; i++)
        cp16f(Bs + r*H_AS + (jb+i)*4, sB + (jb+i)*8);
}

template<bool PERM>
__device__ __forceinline__ void gemm_f16(
    float acc[4][4][4],
    const __half* __restrict__ A, int K,
    const __half* __restrict__ Wt,
    int m0, int n0, const int* __restrict__ perm, float* sm)
{
    const int KT = K / HBK;
    #pragma unroll
    for (int s = 0; s < STAGES-1; s++) {
        if (s < KT) issue_h<PERM>(sm + s*H_STAGE, A, K, Wt, m0, n0, s*HBK, perm);
        cp_commit();
    }
    cp_wait<STAGES-2>();
    __syncthreads();

    const int warp = threadIdx.x >> 5, lane = threadIdx.x & 31;
    const int mw = (warp >> 2) * 64, nw = (warp & 3) * 32;
    const int g = lane >> 2, t4 = lane & 3;

    for (int kt = 0; kt < KT; kt++) {
        const uint32_t* As = (const uint32_t*)(sm + (kt%STAGES)*H_STAGE);
        const uint32_t* Bs = As + H_HALF;
        #pragma unroll
        for (int s = 0; s < HBK/16; s++) {
            const int w0 = s*8 + t4;
            uint32_t af[4][4], bf[4][2];
            #pragma unroll
            for (int mi = 0; mi < 4; mi++) {
                int r = mw + mi*16 + g;
                af[mi][0] = As[(r  )*H_AS + w0];
                af[mi][1] = As[(r+8)*H_AS + w0];
                af[mi][2] = As[(r  )*H_AS + w0 + 4];
                af[mi][3] = As[(r+8)*H_AS + w0 + 4];
            }
            #pragma unroll
            for (int ni = 0; ni < 4; ni++) {
                int c = nw + ni*8 + g;
                bf[ni][0] = Bs[c*H_AS + w0];
                bf[ni][1] = Bs[c*H_AS + w0 + 4];
            }
            #pragma unroll
            for (int mi = 0; mi < 4; mi++)
                #pragma unroll
                for (int ni = 0; ni < 4; ni++)
                    mma16h(acc[mi][ni], af[mi], bf[ni]);
        }
        int pre = kt + STAGES - 1;
        if (pre < KT) issue_h<PERM>(sm + (pre%STAGES)*H_STAGE, A, K, Wt, m0, n0, pre*HBK, perm);
        cp_commit();
        cp_wait<STAGES-2>();
        __syncthreads();
    }
}

#define FRAG_IDX \
    const int warp = threadIdx.x >> 5, lane = threadIdx.x & 31; \
    const int mw = (warp >> 2) * 64, nw = (warp & 3) * 32; \
    const int g = lane >> 2, t4 = lane & 3;

// ---------------- stage kernels ----------------
__global__ void k_four(const float* __restrict__ pos, const float* __restrict__ fB) {
    int gtid = blockIdx.x * 256 + threadIdx.x;
    if (gtid < MAX_TILES*BM) g_perm[gtid] = -1;
    if (gtid < E_NUM) { g_counts[gtid] = 0; g_cursor[gtid] = 0; }

    int w = threadIdx.x >> 5, lane = threadIdx.x & 31;
    int row = blockIdx.x * 8 + w;
    float p0 = pos[row*3+0], p1 = pos[row*3+1], p2 = pos[row*3+2];
    #pragma unroll
    for (int i = 0; i < 4; i++) {
        int c = lane + 32*i;
        float xp = 6.283185307179586477f * (p0*fB[c] + p1*fB[MAP_+c] + p2*fB[2*MAP_+c]);
        float s, co;
        sincosf(xp, &s, &co);
        g_four_h[(size_t)row*256 + c]       = __float2half_rn(s);
        g_four_h[(size_t)row*256 + 128 + c] = __float2half_rn(co);
    }
}

__global__ void __launch_bounds__(NTHREADS, 2)
k_gemm_z(const float* __restrict__ img_b, const float* __restrict__ pos_b) {
    extern __shared__ float sm[];
    float acc[4][4][4] = {};
    int m0 = blockIdx.y * BM, n0 = blockIdx.x * BN;
    FRAG_IDX
    gemm_f16<false>(acc, g_four_h, 256, w_pos_t, m0, n0, nullptr, sm);
    #pragma unroll
    for (int mi = 0; mi < 4; mi++)
        #pragma unroll
        for (int ni = 0; ni < 4; ni++) {
            int c0 = n0 + nw + ni*8 + t4*2;
            acc[mi][ni][0] = gelu_exact(acc[mi][ni][0] + pos_b[c0]);
            acc[mi][ni][1] = gelu_exact(acc[mi][ni][1] + pos_b[c0+1]);
            acc[mi][ni][2] = gelu_exact(acc[mi][ni][2] + pos_b[c0]);
            acc[mi][ni][3] = gelu_exact(acc[mi][ni][3] + pos_b[c0+1]);
        }
    gemm_f16<false>(acc, g_vis_h, 1024, w_img_t, m0, n0, nullptr, sm);
    #pragma unroll
    for (int mi = 0; mi < 4; mi++)
        #pragma unroll
        for (int ni = 0; ni < 4; ni++) {
            int r0 = m0 + mw + mi*16 + g, r1 = r0 + 8;
            int c0 = n0 + nw + ni*8 + t4*2, c1 = c0 + 1;
            float v00 = acc[mi][ni][0] + img_b[c0];
            float v01 = acc[mi][ni][1] + img_b[c1];
            float v10 = acc[mi][ni][2] + img_b[c0];
            float v11 = acc[mi][ni][3] + img_b[c1];
            g_z[(size_t)r0*256 + c0] = v00;  g_z_h[(size_t)r0*256 + c0] = __float2half_rn(v00);
            g_z[(size_t)r0*256 + c1] = v01;  g_z_h[(size_t)r0*256 + c1] = __float2half_rn(v01);
            g_z[(size_t)r1*256 + c0] = v10;  g_z_h[(size_t)r1*256 + c0] = __float2half_rn(v10);
            g_z[(size_t)r1*256 + c1] = v11;  g_z_h[(size_t)r1*256 + c1] = __float2half_rn(v11);
        }
}

__global__ void k_router(const float* __restrict__ grad,
                         const float* __restrict__ rW, const float* __restrict__ rb) {
    int w = threadIdx.x >> 5, lane = threadIdx.x & 31;
    int row = blockIdx.x * 8 + w;
    float4 s = make_float4(0.f,0.f,0.f,0.f);
    #pragma unroll
    for (int i = 0; i < 8; i++) {
        int k = lane + 32*i;
        float zv = g_z[(size_t)row*256 + k];
        float4 wv = *(const float4*)(rW + k*4);
        s.x = fmaf(zv, wv.x, s.x); s.y = fmaf(zv, wv.y, s.y);
        s.z = fmaf(zv, wv.z, s.z); s.w = fmaf(zv, wv.w, s.w);
    }
    #pragma unroll
    for (int off = 16; off; off >>= 1) {
        s.x += __shfl_down_sync(0xffffffffu, s.x, off);
        s.y += __shfl_down_sync(0xffffffffu, s.y, off);
        s.z += __shfl_down_sync(0xffffffffu, s.z, off);
        s.w += __shfl_down_sync(0xffffffffu, s.w, off);
    }
    if (lane == 0) {
        float gv = grad[row];
        float4 wg = *(const float4*)(rW + 256*4);
        float l0 = s.x + gv*wg.x + rb[0];
        float l1 = s.y + gv*wg.y + rb[1];
        float l2 = s.z + gv*wg.z + rb[2];
        float l3 = s.w + gv*wg.w + rb[3];
        float m = l0; int am = 0;
        if (l1 > m) { m = l1; am = 1; }
        if (l2 > m) { m = l2; am = 2; }
        if (l3 > m) { m = l3; am = 3; }
        float sum = expf(l0-m) + expf(l1-m) + expf(l2-m) + expf(l3-m);
        g_eid[row]  = am;
        g_gate[row] = 1.0f / sum;
        atomicAdd(&g_counts[am], 1);
    }
}

__global__ void k_offsets() {
    int off = 0;
    for (int e = 0; e < E_NUM; e++) {
        g_padoff[e] = off;
        off += ((g_counts[e] + BM - 1) / BM) * BM;
    }
    g_padoff[E_NUM] = off;
}

__global__ void k_scatter() {
    int row = blockIdx.x * 256 + threadIdx.x;
    int e = g_eid[row];
    int slot = g_padoff[e] + atomicAdd(&g_cursor[e], 1);
    g_perm[slot] = row;
}

__device__ __forceinline__ int tile_expert(int m0) {
    int e = 0;
    while (e < E_NUM-1 && m0 >= g_padoff[e+1]) e++;
    return e;
}

__global__ void __launch_bounds__(NTHREADS, 2)
k_moe1(const float* __restrict__ eb1) {
    int m0 = blockIdx.y * BM;
    if (m0 >= g_padoff[E_NUM]) return;
    extern __shared__ float sm[];
    int e = tile_expert(m0);
    const __half* W1 = w_e1_t + (size_t)e * 1024 * 256;
    float acc[4][4][4] = {};
    int n0 = blockIdx.x * BN;
    gemm_f16<true>(acc, g_z_h, 256, W1, m0, n0, g_perm, sm);
    FRAG_IDX
    #pragma unroll
    for (int mi = 0; mi < 4; mi++)
        #pragma unroll
        for (int ni = 0; ni < 4; ni++) {
            int r0 = m0 + mw + mi*16 + g, r1 = r0 + 8;
            int c0 = n0 + nw + ni*8 + t4*2, c1 = c0 + 1;
            g_h[(size_t)r0*1024 + c0] = __float2half_rn(gelu_exact(acc[mi][ni][0] + eb1[e*1024 + c0]));
            g_h[(size_t)r0*1024 + c1] = __float2half_rn(gelu_exact(acc[mi][ni][1] + eb1[e*1024 + c1]));
            g_h[(size_t)r1*1024 + c0] = __float2half_rn(gelu_exact(acc[mi][ni][2] + eb1[e*1024 + c0]));
            g_h[(size_t)r1*1024 + c1] = __float2half_rn(gelu_exact(acc[mi][ni][3] + eb1[e*1024 + c1]));
        }
}

__global__ void __launch_bounds__(NTHREADS, 2)
k_moe2(const float* __restrict__ eb2) {
    int m0 = blockIdx.y * BM;
    if (m0 >= g_padoff[E_NUM]) return;
    extern __shared__ float sm[];
    int e = tile_expert(m0);
    const __half* W2 = w_e2_t + (size_t)e * 256 * 1024;
    float acc[4][4][4] = {};
    int n0 = blockIdx.x * BN;
    gemm_f16<false>(acc, g_h, 1024, W2, m0, n0, nullptr, sm);
    FRAG_IDX
    #pragma unroll
    for (int mi = 0; mi < 4; mi++)
        #pragma unroll
        for (int ni = 0; ni < 4; ni++) {
            int s0 = m0 + mw + mi*16 + g, s1 = s0 + 8;
            int c0 = n0 + nw + ni*8 + t4*2, c1 = c0 + 1;
            int r0 = g_perm[s0], r1 = g_perm[s1];
            if (r0 >= 0) {
                float gate = g_gate[r0];
                g_zf_h[(size_t)r0*256 + c0] = __float2half_rn(g_z[(size_t)r0*256 + c0] + gate*(acc[mi][ni][0] + eb2[e*256 + c0]));
                g_zf_h[(size_t)r0*256 + c1] = __float2half_rn(g_z[(size_t)r0*256 + c1] + gate*(acc[mi][ni][1] + eb2[e*256 + c1]));
            }
            if (r1 >= 0) {
                float gate = g_gate[r1];
                g_zf_h[(size_t)r1*256 + c0] = __float2half_rn(g_z[(size_t)r1*256 + c0] + gate*(acc[mi][ni][2] + eb2[e*256 + c0]));
                g_zf_h[(size_t)r1*256 + c1] = __float2half_rn(g_z[(size_t)r1*256 + c1] + gate*(acc[mi][ni][3] + eb2[e*256 + c1]));
            }
        }
}

__global__ void __launch_bounds__(NTHREADS, 2)
k_tpre(const float* __restrict__ b) {
    extern __shared__ float sm[];
    float acc[4][4][4] = {};
    int m0 = blockIdx.y * BM, n0 = blockIdx.x * BN;
    gemm_f16<false>(acc, g_zf_h, 256, w_gd1_t, m0, n0, nullptr, sm);
    FRAG_IDX
    #pragma unroll
    for (int mi = 0; mi < 4; mi++)
        #pragma unroll
        for (int ni = 0; ni < 4; ni++) {
            int r0 = m0 + mw + mi*16 + g, r1 = r0 + 8;
            int c0 = n0 + nw + ni*8 + t4*2, c1 = c0 + 1;
            g_tpre[(size_t)r0*256 + c0] = acc[mi][ni][0] + b[c0];
            g_tpre[(size_t)r0*256 + c1] = acc[mi][ni][1] + b[c1];
            g_tpre[(size_t)r1*256 + c0] = acc[mi][ni][2] + b[c0];
            g_tpre[(size_t)r1*256 + c1] = acc[mi][ni][3] + b[c1];
        }
}

__global__ void k_ln(const float* __restrict__ gam, const float* __restrict__ beta) {
    int w = threadIdx.x >> 5, lane = threadIdx.x & 31;
    int row = blockIdx.x * 8 + w;
    float v[8]; float s = 0.f;
    #pragma unroll
    for (int i = 0; i < 8; i++) {
        v[i] = g_tpre[(size_t)row*256 + lane + 32*i];
        s += v[i];
    }
    #pragma unroll
    for (int off = 16; off; off >>= 1) s += __shfl_xor_sync(0xffffffffu, s, off);
    float mean = s * (1.f/256.f);
    float s2 = 0.f;
    #pragma unroll
    for (int i = 0; i < 8; i++) { float d = v[i] - mean; s2 = fmaf(d, d, s2); }
    #pragma unroll
    for (int off = 16; off; off >>= 1) s2 += __shfl_xor_sync(0xffffffffu, s2, off);
    float rs = rsqrtf(s2 * (1.f/256.f) + 1e-5f);
    #pragma unroll
    for (int i = 0; i < 8; i++) {
        int k = lane + 32*i;
        g_t_h[(size_t)row*256 + k] = __float2half_rn(gelu_exact(gam[k] * (v[i] - mean) * rs + beta[k]));
    }
}

// gd2 with coalesced smem-staged epilogue
__global__ void __launch_bounds__(NTHREADS, 2)
k_gd2(const float* __restrict__ b2,
      const float* __restrict__ lib, float* __restrict__ out) {
    extern __shared__ float sm[];
    float acc[4][4][4] = {};
    int m0 = blockIdx.y * BM, n0 = blockIdx.x * BN;
    gemm_f16<false>(acc, g_t_h, 256, g_wt, m0, n0, nullptr, sm);
    FRAG_IDX
    float* es = sm;
    #pragma unroll
    for (int mi = 0; mi < 4; mi++)
        #pragma unroll
        for (int ni = 0; ni < 4; ni++) {
            int r0 = mw + mi*16 + g, r1 = r0 + 8;
            int c0 = nw + ni*8 + t4*2, c1 = c0 + 1;
            es[r0*ES_STRIDE + c0] = acc[mi][ni][0];
            es[r0*ES_STRIDE + c1] = acc[mi][ni][1];
            es[r1*ES_STRIDE + c0] = acc[mi][ni][2];
            es[r1*ES_STRIDE + c1] = acc[mi][ni][3];
        }
    __syncthreads();
    const size_t THETA_OFF = (size_t)B_ROWS * G_NUM;
    int gbase = n0 >> 1;
    for (int r = warp; r < BM; r += 8) {
        int row = m0 + r;
        float lb = lib[row];
        #pragma unroll
        for (int j = 0; j < 2; j++) {
            int gcol = j*32 + lane;
            int col0 = 2*gcol, col1 = col0 + 1;
            if (n0 + col0 < N_GD2) {
                float v = es[r*ES_STRIDE + col0] + b2[n0 + col0];
                float sp = (v > 20.f) ? v : log1pf(expf(v));
                out[(size_t)row*G_NUM + gbase + gcol] = sp * lb + 1e-6f;
            }
            if (n0 + col1 < N_GD2) {
                float v = es[r*ES_STRIDE + col1] + b2[n0 + col1];
                float sp = (v > 20.f) ? v : log1pf(expf(v));
                out[THETA_OFF + (size_t)row*G_NUM + gbase + gcol] = sp + 1e-6f;
            }
        }
    }
}

// merged align + func hidden with fused second-stage heads.
// block n0=0: a1 (128 cols) -> align out. block n0=128: f1 (64 cols) -> func out.
__global__ void __launch_bounds__(NTHREADS, 2)
k_apfh(const float* __restrict__ apb, const float* __restrict__ fhb,
       const float* __restrict__ apW2, const float* __restrict__ apb2,
       const float* __restrict__ fhW2, const float* __restrict__ fhb2,
       float* __restrict__ out) {
    extern __shared__ float sm[];
    float acc[4][4][4] = {};
    int m0 = blockIdx.y * BM, n0 = blockIdx.x * BN;
    gemm_f16<false>(acc, g_zf_h, 256, w_apfh_t, m0, n0, nullptr, sm);
    FRAG_IDX
    float* es = sm;                       // 128 x ES_STRIDE activation tile
    float* W2s = sm + BM*ES_STRIDE;       // align W2 [128][30]
    float* bs  = W2s + 128*SCVI_;
    const bool is_ap = (n0 == 0);
    #pragma unroll
    for (int mi = 0; mi < 4; mi++)
        #pragma unroll
        for (int ni = 0; ni < 4; ni++) {
            int r0 = mw + mi*16 + g, r1 = r0 + 8;
            int c0 = nw + ni*8 + t4*2, c1 = c0 + 1;
            #pragma unroll
            for (int q = 0; q < 4; q++) {
                int r = (q & 2) ? r1 : r0;
                int c = (q & 1) ? c1 : c0;
                float v = acc[mi][ni][q];
                if (is_ap)
                    es[r*ES_STRIDE + c] = gelu_exact(v + apb[c]);
                else if (c < 64)
                    es[r*ES_STRIDE + c] = gelu_exact(v + fhb[c]);
            }
        }
    if (is_ap) {
        for (int i = threadIdx.x; i < 128*SCVI_; i += NTHREADS) W2s[i] = apW2[i];
        if (threadIdx.x < SCVI_) bs[threadIdx.x] = apb2[threadIdx.x];
    }
    __syncthreads();

    if (is_ap) {
        const size_t ALIGN_OFF = 2ull * B_ROWS * G_NUM + B_ROWS;
        int c = lane;
        for (int r = warp; r < BM; r += 8) {
            if (c < SCVI_) {
                float s = bs[c];
                #pragma unroll 4
                for (int k = 0; k < 128; k++)
                    s = fmaf(es[r*ES_STRIDE + k], W2s[k*SCVI_ + c], s);
                out[ALIGN_OFF + (size_t)(m0 + r)*SCVI_ + c] = s;
            }
        }
    } else {
        const size_t FUNC_OFF = 2ull * B_ROWS * G_NUM;
        float w0 = fhW2[lane], w1 = fhW2[lane + 32];
        float bb = fhb2[0];
        for (int r = warp; r < BM; r += 8) {
            float v = es[r*ES_STRIDE + lane] * w0 + es[r*ES_STRIDE + lane + 32] * w1;
            #pragma unroll
            for (int off = 16; off; off >>= 1) v += __shfl_down_sync(0xffffffffu, v, off);
            if (lane == 0)
                out[FUNC_OFF + (m0 + r)] = 1.f / (1.f + expf(-(v + bb)));
        }
    }
}

// ---------------- launch ----------------
extern "C" void kernel_launch(void* const* d_in, const int* in_sizes, int n_in,
                              void* d_out, int out_size) {
    const float* vis   = (const float*)d_in[0];
    const float* pos   = (const float*)d_in[1];
    const float* grad  = (const float*)d_in[2];
    const float* lib   = (const float*)d_in[3];
    const float* fB    = (const float*)d_in[4];
    const float* img_W = (const float*)d_in[5];
    const float* img_b = (const float*)d_in[6];
    const float* pos_W = (const float*)d_in[7];
    const float* pos_b = (const float*)d_in[8];
    const float* rW    = (const float*)d_in[9];
    const float* rb    = (const float*)d_in[10];
    const float* eW1   = (const float*)d_in[11];
    const float* eb1   = (const float*)d_in[12];
    const float* eW2   = (const float*)d_in[13];
    const float* eb2   = (const float*)d_in[14];
    const float* gdW1  = (const float*)d_in[15];
    const float* gdb1  = (const float*)d_in[16];
    const float* gdg   = (const float*)d_in[17];
    const float* gdbe  = (const float*)d_in[18];
    const float* gdW2  = (const float*)d_in[19];
    const float* gdb2  = (const float*)d_in[20];
    const float* apW1  = (const float*)d_in[21];
    const float* apb1  = (const float*)d_in[22];
    const float* apW2  = (const float*)d_in[23];
    const float* apb2  = (const float*)d_in[24];
    const float* fhW1  = (const float*)d_in[25];
    const float* fhb1  = (const float*)d_in[26];
    const float* fhW2  = (const float*)d_in[27];
    const float* fhb2  = (const float*)d_in[28];
    float* out = (float*)d_out;

    cudaFuncSetAttribute(k_gemm_z, cudaFuncAttributeMaxDynamicSharedMemorySize, H_SMEM);
    cudaFuncSetAttribute(k_moe1,   cudaFuncAttributeMaxDynamicSharedMemorySize, H_SMEM);
    cudaFuncSetAttribute(k_moe2,   cudaFuncAttributeMaxDynamicSharedMemorySize, H_SMEM);
    cudaFuncSetAttribute(k_tpre,   cudaFuncAttributeMaxDynamicSharedMemorySize, H_SMEM);
    cudaFuncSetAttribute(k_gd2,    cudaFuncAttributeMaxDynamicSharedMemorySize, H_SMEM);
    cudaFuncSetAttribute(k_apfh,   cudaFuncAttributeMaxDynamicSharedMemorySize, H_SMEM);

    __half *iw, *e1w, *e2w, *g2w;
    cudaGetSymbolAddress((void**)&iw,  w_img_t);
    cudaGetSymbolAddress((void**)&e1w, w_e1_t);
    cudaGetSymbolAddress((void**)&e2w, w_e2_t);
    cudaGetSymbolAddress((void**)&g2w, g_wt);

    // weight prep
    k_trh4<<<dim3(8, 8, 4), 256>>>(pos_W, gdW1, apW1, fhW1);
    k_trh<<<dim3(8, 32, 1), 256>>>(img_W, iw, 1024, 256, 256, 0, 0);
    k_trh<<<dim3(32, 8, E_NUM), 256>>>(eW1, e1w, 256, 1024, 1024, (size_t)256*1024, (size_t)1024*256);
    k_trh<<<dim3(8, 32, E_NUM), 256>>>(eW2, e2w, 1024, 256, 256, (size_t)1024*256, (size_t)256*1024);
    k_trh<<<dim3(316, 8, 1), 256>>>(gdW2, g2w, 256, N_GD2, NT_PAD, 0, 0);
    k_vish<<<(B_ROWS*D_VIS/4 + 255)/256, 256>>>(vis, B_ROWS*D_VIS/4);

    k_four   <<<B_ROWS/8, 256>>>(pos, fB);
    k_gemm_z <<<dim3(2, B_ROWS/BM), NTHREADS, H_SMEM>>>(img_b, pos_b);
    k_router <<<B_ROWS/8, 256>>>(grad, rW, rb);
    k_offsets<<<1,1>>>();
    k_scatter<<<B_ROWS/256, 256>>>();
    k_moe1   <<<dim3(8, MAX_TILES), NTHREADS, H_SMEM>>>(eb1);
    k_moe2   <<<dim3(2, MAX_TILES), NTHREADS, H_SMEM>>>(eb2);
    k_tpre   <<<dim3(2, B_ROWS/BM), NTHREADS, H_SMEM>>>(gdb1);
    k_ln     <<<B_ROWS/8, 256>>>(gdg, gdbe);
    k_gd2    <<<dim3(NT_PAD/BN, B_ROWS/BM), NTHREADS, H_SMEM>>>(gdb2, lib, out);
    k_apfh   <<<dim3(2, B_ROWS/BM), NTHREADS, H_SMEM>>>(apb1, fhb1, apW2, apb2, fhW2, fhb2, out);
}